// round 9
// baseline (speedup 1.0000x reference)
#include <cuda_runtime.h>
#include <cuda_bf16.h>
#include <cuda_fp16.h>
#include <math.h>
#include <stdint.h>

#define F 256
#define NW 512           // fused B width: [W_self | W]
#define N_MAX 50048
#define E_MAX 800256

// -------- device scratch --------
__device__ float g_sin[N_MAX];               // in_deg^-1/2
__device__ float g_outr[N_MAX];              // out_deg^-1/2
__device__ int   g_cnt[N_MAX];
__device__ int   g_outd[N_MAX];
__device__ int   g_fill[N_MAX];
__device__ int   g_roff[N_MAX + 1];
__device__ int   g_esrc[E_MAX];
__device__ float g_esc[E_MAX];
__device__ int   g_sstate[64];               // lookback scan state

__device__ __half g_featH[(size_t)N_MAX * F];       // fp16 hi
__device__ __half g_featL[(size_t)N_MAX * F];       // fp16 residual
__device__ __half g_wb[F * NW];                     // [k][n512] = [W_self | W]
__device__ __half g_h0[(size_t)N_MAX * F];          // feature@W_self (fp16)
__device__ __half g_h1[(size_t)N_MAX * F];          // feature@W      (fp16)

// -------- helpers --------
__device__ __forceinline__ uint32_t sptr(const void* p) {
    return (uint32_t)__cvta_generic_to_shared(p);
}
__device__ __forceinline__ void ldsm4(unsigned r[4], uint32_t a) {
    asm volatile("ldmatrix.sync.aligned.m8n8.x4.shared.b16 {%0,%1,%2,%3}, [%4];\n"
        : "=r"(r[0]), "=r"(r[1]), "=r"(r[2]), "=r"(r[3]) : "r"(a));
}
__device__ __forceinline__ void ldsm4t(unsigned r[4], uint32_t a) {
    asm volatile("ldmatrix.sync.aligned.m8n8.x4.trans.shared.b16 {%0,%1,%2,%3}, [%4];\n"
        : "=r"(r[0]), "=r"(r[1]), "=r"(r[2]), "=r"(r[3]) : "r"(a));
}
__device__ __forceinline__ void mma_f16(float* d, const unsigned a[4],
                                        unsigned b0, unsigned b1) {
    asm volatile(
        "mma.sync.aligned.m16n8k16.row.col.f32.f16.f16.f32 "
        "{%0,%1,%2,%3}, {%4,%5,%6,%7}, {%8,%9}, {%0,%1,%2,%3};\n"
        : "+f"(d[0]), "+f"(d[1]), "+f"(d[2]), "+f"(d[3])
        : "r"(a[0]), "r"(a[1]), "r"(a[2]), "r"(a[3]), "r"(b0), "r"(b1));
}
__device__ __forceinline__ void cp16(uint32_t dst, const void* src) {
    asm volatile("cp.async.cg.shared.global [%0], [%1], 16;\n" :: "r"(dst), "l"(src));
}
__device__ __forceinline__ void cp16z(uint32_t dst, const void* src, int sz) {
    asm volatile("cp.async.cg.shared.global [%0], [%1], 16, %2;\n"
                 :: "r"(dst), "l"(src), "r"(sz));
}
__device__ __forceinline__ void cp_commit() {
    asm volatile("cp.async.commit_group;\n" ::: "memory");
}
__device__ __forceinline__ void cp_wait1() {
    asm volatile("cp.async.wait_group 1;\n" ::: "memory");
}
__device__ __forceinline__ void cp_wait0() {
    asm volatile("cp.async.wait_group 0;\n" ::: "memory");
}

// ---------------- zero ----------------
__global__ void zero_kernel(int n) {
    int i = blockIdx.x * blockDim.x + threadIdx.x;
    if (i < n) { g_cnt[i] = 0; g_outd[i] = 0; }
    if (i < 64) g_sstate[i] = 0;
}

// ---------------- fused: hist | convert feature | convert W ----------------
__global__ void phaseA_kernel(const int* __restrict__ src,
                              const int* __restrict__ dst,
                              const float* __restrict__ feat,
                              const float* __restrict__ Ws,
                              const float* __restrict__ Wn,
                              int e, int q, int HB, int CB) {
    int b = blockIdx.x, t = threadIdx.x;
    if (b < HB) {
        int i = b * 256 + t;
        if (i < e) {
            atomicAdd(&g_cnt[dst[i]], 1);
            atomicAdd(&g_outd[src[i]], 1);
        }
    } else if (b < HB + CB) {
        int i = (b - HB) * 256 + t;
        if (i < q) {
            float4 v = ((const float4*)feat)[i];
            __half h0 = __float2half_rn(v.x), h1 = __float2half_rn(v.y);
            __half h2 = __float2half_rn(v.z), h3 = __float2half_rn(v.w);
            __half l0 = __float2half_rn(v.x - __half2float(h0));
            __half l1 = __float2half_rn(v.y - __half2float(h1));
            __half l2 = __float2half_rn(v.z - __half2float(h2));
            __half l3 = __float2half_rn(v.w - __half2float(h3));
            __half2 H0 = __halves2half2(h0, h1), H1 = __halves2half2(h2, h3);
            __half2 L0 = __halves2half2(l0, l1), L1 = __halves2half2(l2, l3);
            ((uint2*)g_featH)[i] = make_uint2(*(unsigned*)&H0, *(unsigned*)&H1);
            ((uint2*)g_featL)[i] = make_uint2(*(unsigned*)&L0, *(unsigned*)&L1);
        }
    } else {
        int i = (b - HB - CB) * 256 + t;
        if (i < F * F) {
            int k = i >> 8, nn = i & 255;
            g_wb[k * NW + nn]       = __float2half_rn(Ws[i]);
            g_wb[k * NW + 256 + nn] = __float2half_rn(Wn[i]);
        }
    }
}

// ---------------- single-pass scan (decoupled lookback, <=64 blocks) -------
// All blocks resident (49 <= 148 SMs) -> spin is safe.
__global__ void __launch_bounds__(1024)
scan_fused_kernel(int n) {
    __shared__ int sh[1024];
    __shared__ int s_pre;
    int b = blockIdx.x, t = threadIdx.x;
    int i = b * 1024 + t;
    int cnt = (i < n) ? g_cnt[i] : 0;
    sh[t] = cnt; __syncthreads();
    #pragma unroll
    for (int off = 1; off < 1024; off <<= 1) {
        int x = sh[t];
        if (t >= off) x += sh[t - off];
        __syncthreads();
        sh[t] = x;
        __syncthreads();
    }
    int incl = sh[t];
    int total = sh[1023];

    if (t == 0) {
        volatile int* st = g_sstate;
        if (b == 0) {
            st[0] = (total << 2) | 2;
            s_pre = 0;
        } else {
            st[b] = (total << 2) | 1;          // publish aggregate
            int pre = 0;
            int j = b - 1;
            while (j >= 0) {
                int v = st[j];
                int f = v & 3;
                if (f == 2) { pre += (v >> 2); break; }
                if (f == 1) { pre += (v >> 2); --j; }
            }
            st[b] = ((total + pre) << 2) | 2;  // upgrade to inclusive
            s_pre = pre;
        }
    }
    __syncthreads();
    int incl_g = incl + s_pre;
    if (i < n) {
        g_roff[i + 1] = incl_g;
        g_fill[i] = incl_g - cnt;
        g_outr[i] = rsqrtf(fmaxf((float)g_outd[i], 1.0f));
        g_sin[i]  = rsqrtf(fmaxf((float)cnt, 1.0f));
        if (i == 0) g_roff[0] = 0;
    }
}

__global__ void fill_kernel(const int* __restrict__ src,
                            const int* __restrict__ dst,
                            const float* __restrict__ e_w,
                            float* __restrict__ out_tail, int e) {
    int i = blockIdx.x * blockDim.x + threadIdx.x;
    if (i < e) {
        float w = e_w[i];
        int s = src[i];
        int p = atomicAdd(&g_fill[dst[i]], 1);
        g_esrc[p] = s;
        g_esc[p] = w * g_outr[s];
        out_tail[i] = w;               // e_w passthrough output
    }
}

// ---------------- fp16 GEMM (mma.sync, 3-stage cp.async) -------------------
// Y[n,512] = feature @ [W_self | W]; tn<2 -> g_h0 (2-term hi+lo split),
// tn>=2 -> g_h1 (1-term hi only). Both stored fp16.
#define A_STRIDE 40
#define B_STRIDE 136
#define ST_ELEMS 14592           // 2*128*40 + 32*136
#define AH_OFF(s) ((s) * ST_ELEMS)
#define AL_OFF(s) ((s) * ST_ELEMS + 5120)
#define BH_OFF(s) ((s) * ST_ELEMS + 10240)
#define NSTAGE 3
#define SMEM_DYN (NSTAGE * ST_ELEMS * 2)

__device__ __forceinline__ void load_stage(uint32_t sb, int stage, int it,
                                           int mBase, int nBase, int n, int tid,
                                           bool needL) {
    int k0 = it * 32;
    #pragma unroll
    for (int u = 0; u < 2; ++u) {
        int idx = u * 256 + tid;
        int row = idx >> 2, un = idx & 3;
        int gr = mBase + row;
        int grc = min(gr, n - 1);
        size_t go = (size_t)grc * F + k0 + un * 8;
        int sz = (gr < n) ? 16 : 0;
        uint32_t doff = (uint32_t)(row * A_STRIDE + un * 8) * 2;
        cp16z(sb + (uint32_t)AH_OFF(stage) * 2 + doff, g_featH + go, sz);
        if (needL)
            cp16z(sb + (uint32_t)AL_OFF(stage) * 2 + doff, g_featL + go, sz);
    }
    #pragma unroll
    for (int u = 0; u < 2; ++u) {
        int idx = u * 256 + tid;
        int row = idx >> 4, un = idx & 15;
        size_t go = (size_t)(k0 + row) * NW + nBase + un * 8;
        uint32_t doff = (uint32_t)(row * B_STRIDE + un * 8) * 2;
        cp16(sb + (uint32_t)BH_OFF(stage) * 2 + doff, g_wb + go);
    }
}

__global__ void __launch_bounds__(256, 2)
gemm_kernel(int n) {
    extern __shared__ __align__(128) char smraw[];
    __half* base = (__half*)smraw;
    uint32_t sb = sptr(smraw);

    int tid = threadIdx.x;
    int wid = tid >> 5, lane = tid & 31;
    int wm = wid & 3, wn = wid >> 2;
    int t = blockIdx.x;
    int mBase = (t >> 2) * 128;
    int tn = t & 3;
    int nBase = tn * 128;
    const bool needL = (tn < 2);       // 2-term split only for the h_s half

    float acc[2][8][4];
    #pragma unroll
    for (int i = 0; i < 2; ++i)
        #pragma unroll
        for (int j = 0; j < 8; ++j)
            #pragma unroll
            for (int q = 0; q < 4; ++q) acc[i][j][q] = 0.f;

    load_stage(sb, 0, 0, mBase, nBase, n, tid, needL); cp_commit();
    load_stage(sb, 1, 1, mBase, nBase, n, tid, needL); cp_commit();

    #pragma unroll 1
    for (int it = 0; it < 8; ++it) {
        if (it < 7) cp_wait1(); else cp_wait0();
        __syncthreads();
        int st = it % NSTAGE;
        #pragma unroll
        for (int kt = 0; kt < 2; ++kt) {
            int ks = kt * 16;
            unsigned aH[2][4], aL[2][4];
            #pragma unroll
            for (int mt = 0; mt < 2; ++mt) {
                int r = wm * 32 + mt * 16 + (lane & 15);
                int c = ks + (lane >> 4) * 8;
                ldsm4(aH[mt], sptr(base + AH_OFF(st) + r * A_STRIDE + c));
                if (needL)
                    ldsm4(aL[mt], sptr(base + AL_OFF(st) + r * A_STRIDE + c));
            }
            #pragma unroll
            for (int nc = 0; nc < 4; ++nc) {
                int rB = ks + (lane & 15);
                int cB = wn * 64 + nc * 16 + (lane >> 4) * 8;
                unsigned bH[4];
                ldsm4t(bH, sptr(base + BH_OFF(st) + rB * B_STRIDE + cB));
                #pragma unroll
                for (int mt = 0; mt < 2; ++mt) {
                    mma_f16(acc[mt][nc * 2],     aH[mt], bH[0], bH[1]);
                    mma_f16(acc[mt][nc * 2 + 1], aH[mt], bH[2], bH[3]);
                    if (needL) {
                        mma_f16(acc[mt][nc * 2],     aL[mt], bH[0], bH[1]);
                        mma_f16(acc[mt][nc * 2 + 1], aL[mt], bH[2], bH[3]);
                    }
                }
            }
        }
        if (it + 2 < 8) {
            load_stage(sb, (it + 2) % NSTAGE, it + 2, mBase, nBase, n, tid, needL);
            cp_commit();
        }
    }

    // epilogue: fp16 to g_h0 (tn<2) or g_h1 (tn>=2)
    __half* dstp = (tn < 2) ? g_h0 : g_h1;
    #pragma unroll
    for (int mt = 0; mt < 2; ++mt) {
        int r0 = mBase + wm * 32 + mt * 16 + (lane >> 2);
        int r1 = r0 + 8;
        #pragma unroll
        for (int nt = 0; nt < 8; ++nt) {
            int cl = wn * 64 + nt * 8 + (lane & 3) * 2;
            int c = (tn & 1) * 128 + cl;
            float* d = acc[mt][nt];
            if (r0 < n) {
                __half2 v = __floats2half2_rn(d[0], d[1]);
                *(unsigned*)(dstp + (size_t)r0 * F + c) = *(unsigned*)&v;
            }
            if (r1 < n) {
                __half2 v = __floats2half2_rn(d[2], d[3]);
                *(unsigned*)(dstp + (size_t)r1 * F + c) = *(unsigned*)&v;
            }
        }
    }
}

// ---------------- final: out = h0 + si*(S . h1) + si*b (write-only out) ----
__global__ void __launch_bounds__(512)
final_kernel(const float* __restrict__ bias, float* __restrict__ out, int n) {
    int row  = blockIdx.x * 16 + (threadIdx.x >> 5);
    int lane = threadIdx.x & 31;
    if (row >= n) return;
    int beg = g_roff[row], end = g_roff[row + 1];
    float a[8];
    #pragma unroll
    for (int j = 0; j < 8; ++j) a[j] = 0.f;
    for (int base = beg; base < end; base += 32) {
        int m = min(32, end - base);
        int sE = 0; float cE = 0.f;
        if (lane < m) { sE = g_esrc[base + lane]; cE = g_esc[base + lane]; }
        #pragma unroll 4
        for (int j = 0; j < m; ++j) {
            int   ss = __shfl_sync(0xffffffffu, sE, j);
            float sc = __shfl_sync(0xffffffffu, cE, j);
            uint4 d = *(const uint4*)(g_h1 + (size_t)ss * F + lane * 8);
            float2 f0 = __half22float2(*(__half2*)&d.x);
            float2 f1 = __half22float2(*(__half2*)&d.y);
            float2 f2 = __half22float2(*(__half2*)&d.z);
            float2 f3 = __half22float2(*(__half2*)&d.w);
            a[0] += f0.x * sc; a[1] += f0.y * sc;
            a[2] += f1.x * sc; a[3] += f1.y * sc;
            a[4] += f2.x * sc; a[5] += f2.y * sc;
            a[6] += f3.x * sc; a[7] += f3.y * sc;
        }
    }
    float si = g_sin[row];
    uint4 h = *(const uint4*)(g_h0 + (size_t)row * F + lane * 8);
    float2 s0 = __half22float2(*(__half2*)&h.x);
    float2 s1 = __half22float2(*(__half2*)&h.y);
    float2 s2 = __half22float2(*(__half2*)&h.z);
    float2 s3 = __half22float2(*(__half2*)&h.w);
    float4 b0 = *(const float4*)(bias + lane * 8);
    float4 b1 = *(const float4*)(bias + lane * 8 + 4);
    float4 o0, o1;
    o0.x = s0.x + si * (a[0] + b0.x); o0.y = s0.y + si * (a[1] + b0.y);
    o0.z = s1.x + si * (a[2] + b0.z); o0.w = s1.y + si * (a[3] + b0.w);
    o1.x = s2.x + si * (a[4] + b1.x); o1.y = s2.y + si * (a[5] + b1.y);
    o1.z = s3.x + si * (a[6] + b1.z); o1.w = s3.y + si * (a[7] + b1.w);
    float* op = out + (size_t)row * F + lane * 8;
    *(float4*)(op)     = o0;
    *(float4*)(op + 4) = o1;
}

// ---------------- launch ----------------
extern "C" void kernel_launch(void* const* d_in, const int* in_sizes, int n_in,
                              void* d_out, int out_size) {
    const float* feature = (const float*)d_in[0];
    const float* e_w     = (const float*)d_in[1];
    const float* W_self  = (const float*)d_in[4];
    const float* W       = (const float*)d_in[5];
    const float* b       = (const float*)d_in[6];
    const int*   src     = (const int*)d_in[7];
    const int*   dst     = (const int*)d_in[8];
    float*       out     = (float*)d_out;

    int n = in_sizes[0] / F;
    int e = in_sizes[1];
    int q = n * (F / 4);

    static bool init = false;
    static cudaStream_t s2 = 0;
    static cudaEvent_t ev1 = 0, ev2 = 0;
    if (!init) {
        cudaFuncSetAttribute(gemm_kernel,
                             cudaFuncAttributeMaxDynamicSharedMemorySize, SMEM_DYN);
        cudaStreamCreateWithFlags(&s2, cudaStreamNonBlocking);
        cudaEventCreateWithFlags(&ev1, cudaEventDisableTiming);
        cudaEventCreateWithFlags(&ev2, cudaEventDisableTiming);
        init = true;
    }

    cudaStream_t ms = 0;
    {
        cudaStreamCaptureStatus cs = cudaStreamCaptureStatusNone;
        if (cudaStreamIsCapturing(cudaStreamPerThread, &cs) == cudaSuccess &&
            cs == cudaStreamCaptureStatusActive)
            ms = cudaStreamPerThread;
    }

    // K1: zero counters + scan state
    zero_kernel<<<(n + 255) / 256, 256, 0, ms>>>(n);

    // K2: fused hist | convert feature | convert W (guaranteed co-scheduled)
    int HB = (e + 255) / 256;
    int CB = (q + 255) / 256;
    int WB = (F * F + 255) / 256;
    phaseA_kernel<<<HB + CB + WB, 256, 0, ms>>>(src, dst, feature, W_self, W,
                                                e, q, HB, CB);

    // fork: scan + fill on side stream (hidden under GEMM if fork overlaps)
    cudaEventRecord(ev1, ms);
    cudaStreamWaitEvent(s2, ev1, 0);
    int NB = (n + 1023) / 1024;     // <= 64
    scan_fused_kernel<<<NB, 1024, 0, s2>>>(n);
    fill_kernel<<<(e + 255) / 256, 256, 0, s2>>>(src, dst, e_w,
                                                 out + (size_t)n * F, e);
    cudaEventRecord(ev2, s2);

    // main: GEMM
    int NT = ((n + 127) / 128) * 4;
    gemm_kernel<<<NT, 256, SMEM_DYN, ms>>>(n);

    // join + final
    cudaStreamWaitEvent(ms, ev2, 0);
    final_kernel<<<(n + 15) / 16, 512, 0, ms>>>(b, out, n);
}